// round 7
// baseline (speedup 1.0000x reference)
#include <cuda_runtime.h>
#include <cuda_fp16.h>

namespace {
constexpr int B = 16, S = 512, HID = 512, NH = 8, DK = 64, TH = 32, TE = 16;
constexpr int BH = 128;
constexpr float SC2 = 0.125f * 1.44269504088896f;  // scale * log2(e)
constexpr int QN = 8192 * 512;
constexpr int WN = 512 * 512;
}

// ---------------- scratch (device globals; no runtime allocation) -------------
__device__ __half g_In16[3][QN];                     // q,k,v as half
__device__ __half g_W16[4][WN];                      // Wq,Wk,Wv,Wo as half
__device__ __half g_Qh[BH * S * DK];
__device__ __half g_Kh[BH * S * DK];
__device__ __half g_VhT[BH * DK * S];                // V transposed: [bh][d][s]
__device__ __half g_QHop16[BH * S * TH];
__device__ __half g_KHop16[BH * S * TH];
__device__ __half g_EB16[BH * S * TE];
__device__ __half g_OutH[BH * S * DK];
__device__ unsigned short g_DE16[(size_t)B * S * S];

// ---------------- helpers -----------------------------------------------------
__device__ __forceinline__ unsigned pack_half2(float x, float y) {
  __half2 h = __floats2half2_rn(x, y);
  return *reinterpret_cast<unsigned*>(&h);
}
__device__ __forceinline__ float fast_exp2(float x) {
  asm("ex2.approx.f32 %0, %0;" : "+f"(x));
  return x;
}
__device__ __forceinline__ void mma_f16(float* c, const unsigned* a, const unsigned* b) {
  asm volatile(
      "mma.sync.aligned.m16n8k16.row.col.f32.f16.f16.f32 "
      "{%0,%1,%2,%3}, {%4,%5,%6,%7}, {%8,%9}, {%0,%1,%2,%3};\n"
      : "+f"(c[0]), "+f"(c[1]), "+f"(c[2]), "+f"(c[3])
      : "r"(a[0]), "r"(a[1]), "r"(a[2]), "r"(a[3]), "r"(b[0]), "r"(b[1]));
}
__device__ __forceinline__ void cpa16(void* sm, const void* gm) {
  unsigned s = (unsigned)__cvta_generic_to_shared(sm);
  asm volatile("cp.async.ca.shared.global [%0], [%1], 16;\n" :: "r"(s), "l"(gm));
}
__device__ __forceinline__ void cp_commit() { asm volatile("cp.async.commit_group;\n"); }
__device__ __forceinline__ void cp_wait1() { asm volatile("cp.async.wait_group 1;\n"); }
__device__ __forceinline__ void cp_wait0() { asm volatile("cp.async.wait_group 0;\n"); }

// ---------------- fused convert (f32->half) + pack (dist|edge -> u16) ---------
__global__ __launch_bounds__(256) void prep_kernel(
    const float* __restrict__ q, const float* __restrict__ k, const float* __restrict__ v,
    const float* __restrict__ Wq, const float* __restrict__ Wk,
    const float* __restrict__ Wv, const float* __restrict__ Wo,
    const int* __restrict__ dist, const int* __restrict__ edge) {
  const int QU = QN / 8, WU = WN / 8;
  const int cv_total = 3 * QU + 4 * WU;
  const int n4 = B * S * S / 4;
  int i = blockIdx.x * 256 + threadIdx.x;
  if (i < cv_total) {
    const float* src; __half* dst; int off;
    if (i < 3 * QU) {
      int z = i / QU; off = (i - z * QU) * 8;
      src = (z == 0) ? q : (z == 1) ? k : v;
      dst = g_In16[z];
    } else {
      int j = i - 3 * QU; int z = j / WU; off = (j - z * WU) * 8;
      src = (z == 0) ? Wq : (z == 1) ? Wk : (z == 2) ? Wv : Wo;
      dst = g_W16[z];
    }
    float4 a = *reinterpret_cast<const float4*>(src + off);
    float4 b2 = *reinterpret_cast<const float4*>(src + off + 4);
    uint4 o;
    o.x = pack_half2(a.x, a.y);  o.y = pack_half2(a.z, a.w);
    o.z = pack_half2(b2.x, b2.y); o.w = pack_half2(b2.z, b2.w);
    *reinterpret_cast<uint4*>(dst + off) = o;
  } else {
    int j = i - cv_total;
    if (j >= n4) return;
    int4 d = reinterpret_cast<const int4*>(dist)[j];
    int4 e = reinterpret_cast<const int4*>(edge)[j];
    ushort4 o;
    o.x = (unsigned short)(d.x | (e.x << 8));
    o.y = (unsigned short)(d.y | (e.y << 8));
    o.z = (unsigned short)(d.z | (e.z << 8));
    o.w = (unsigned short)(d.w | (e.w << 8));
    reinterpret_cast<ushort4*>(g_DE16)[j] = o;
  }
}

// ---------------- proj GEMM (double-buffered cp.async, fp16 mma) --------------
// MODE 0: z=blockIdx.z in {0,1,2} -> Qh/Kh/VhT.  MODE 1: out proj (f32 out).
template <int MODE>
__global__ __launch_bounds__(256) void proj_mma(
    const float* __restrict__ bias0, const float* __restrict__ bias1,
    const float* __restrict__ bias2, float* __restrict__ Cout) {
  extern __shared__ __half psm[];
  __half* Abuf[2] = { psm, psm + 128 * 72 };
  __half* Wbuf[2] = { psm + 2 * 128 * 72, psm + 2 * 128 * 72 + 64 * 72 };
  const int z = (MODE == 0) ? blockIdx.z : 3;
  const __half* A = (MODE == 0) ? g_In16[z] : g_OutH;
  const __half* W = g_W16[z];
  const float* bias = (MODE == 0) ? (z == 0 ? bias0 : (z == 1 ? bias1 : bias2)) : bias0;
  const int m0 = blockIdx.y * 128, n0 = blockIdx.x * 64;
  const int tid = threadIdx.x, lane = tid & 31, wid = tid >> 5;
  const int wm = wid & 3, wn = wid >> 2, g = lane >> 2, t4 = lane & 3;
  const int bbM = m0 >> 9, ii0 = m0 & 511;
  float c[2][4][4] = {};

  auto issue = [&](int s, int buf) {
#pragma unroll
    for (int i = 0; i < 4; i++) {
      int idx = tid + i * 256;
      int r = idx >> 3, c8 = (idx & 7) * 8;
      const __half* gp;
      if (MODE == 0) gp = A + (m0 + r) * 512 + s * 64 + c8;
      else {
        int n = m0 + r, bb = n >> 9, ii = n & 511;
        gp = g_OutH + ((bb * NH + s) * S + ii) * DK + c8;
      }
      cpa16(Abuf[buf] + r * 72 + c8, gp);
    }
#pragma unroll
    for (int i = 0; i < 2; i++) {
      int idx = tid + i * 256;
      int r = idx >> 3, c8 = (idx & 7) * 8;
      cpa16(Wbuf[buf] + r * 72 + c8, W + (n0 + r) * 512 + s * 64 + c8);
    }
    cp_commit();
  };

  issue(0, 0);
  for (int s = 0; s < 8; s++) {
    const int buf = s & 1;
    if (s < 7) { issue(s + 1, buf ^ 1); cp_wait1(); } else { cp_wait0(); }
    __syncthreads();
    const unsigned* Ar = reinterpret_cast<const unsigned*>(Abuf[buf]);
    const unsigned* Wr = reinterpret_cast<const unsigned*>(Wbuf[buf]);
#pragma unroll
    for (int k16 = 0; k16 < 4; k16++) {
      const int kw = k16 * 8;
      unsigned a[2][4], b[4][2];
#pragma unroll
      for (int mi = 0; mi < 2; mi++) {
        const int rr = wm * 32 + mi * 16 + g;
        a[mi][0] = Ar[rr * 36 + kw + t4];       a[mi][1] = Ar[(rr + 8) * 36 + kw + t4];
        a[mi][2] = Ar[rr * 36 + kw + 4 + t4];   a[mi][3] = Ar[(rr + 8) * 36 + kw + 4 + t4];
      }
#pragma unroll
      for (int ni = 0; ni < 4; ni++) {
        const int cc = wn * 32 + ni * 8 + g;
        b[ni][0] = Wr[cc * 36 + kw + t4]; b[ni][1] = Wr[cc * 36 + kw + 4 + t4];
      }
#pragma unroll
      for (int mi = 0; mi < 2; mi++)
#pragma unroll
        for (int ni = 0; ni < 4; ni++) mma_f16(c[mi][ni], a[mi], b[ni]);
    }
    __syncthreads();
  }

  if (MODE == 0 && z == 2) {
    __half* Vst = psm;  // [64][136]
#pragma unroll
    for (int mi = 0; mi < 2; mi++)
#pragma unroll
      for (int ni = 0; ni < 4; ni++)
#pragma unroll
        for (int hf = 0; hf < 2; hf++) {
          const int rl = wm * 32 + mi * 16 + g + hf * 8;
          const int d = wn * 32 + ni * 8 + t4 * 2;
          Vst[d * 136 + rl]       = __float2half_rn(c[mi][ni][hf * 2 + 0] + bias[n0 + d]);
          Vst[(d + 1) * 136 + rl] = __float2half_rn(c[mi][ni][hf * 2 + 1] + bias[n0 + d + 1]);
        }
    __syncthreads();
    const int d = tid >> 2, q32 = tid & 3;
    const uint4* srcp = reinterpret_cast<const uint4*>(Vst + d * 136 + q32 * 32);
    __half* dstp = g_VhT + (size_t)((bbM * NH + (n0 >> 6)) * DK + d) * S + ii0 + q32 * 32;
#pragma unroll
    for (int i = 0; i < 4; i++) reinterpret_cast<uint4*>(dstp)[i] = srcp[i];
    return;
  }

#pragma unroll
  for (int mi = 0; mi < 2; mi++)
#pragma unroll
    for (int ni = 0; ni < 4; ni++)
#pragma unroll
      for (int hf = 0; hf < 2; hf++) {
        const int row = m0 + wm * 32 + mi * 16 + g + hf * 8;
        const int col = n0 + wn * 32 + ni * 8 + t4 * 2;
        const float v0 = c[mi][ni][hf * 2 + 0] + bias[col];
        const float v1 = c[mi][ni][hf * 2 + 1] + bias[col + 1];
        if (MODE == 1) {
          *reinterpret_cast<float2*>(&Cout[row * 512 + col]) = make_float2(v0, v1);
        } else {
          const int bb = row >> 9, ii = row & 511, h = col >> 6, d = col & 63;
          __half* dst = (z == 0) ? g_Qh : g_Kh;
          *reinterpret_cast<__half2*>(&dst[(((bb * NH + h) * S) + ii) * DK + d]) =
              __floats2half2_rn(v0, v1);
        }
      }
}

// ---------------- tables: QHop/KHop/EB via fp16 mma (half outputs) ------------
__global__ __launch_bounds__(256) void tables_mma(
    const float* __restrict__ qhe, const float* __restrict__ qee,
    const float* __restrict__ khe, const float* __restrict__ kee) {
  __shared__ unsigned Qs[64][36];
  __shared__ unsigned Ks2[64][36];
  __shared__ unsigned Eq[48][36];
  __shared__ unsigned Ek[48][36];
  const int bh = blockIdx.x, h = bh & 7;
  const int i0 = blockIdx.y * 64;
  const int tid = threadIdx.x;
  const int lane = tid & 31, wid = tid >> 5;
  const int wm = wid & 3, wn = wid >> 2;
  const int g = lane >> 2, t4 = lane & 3;

  for (int i = tid; i < 64 * 16; i += 256) {
    const int r = i >> 4, u = i & 15;
    uint2 q = *reinterpret_cast<const uint2*>(&g_Qh[(bh * S + i0 + r) * DK + u * 4]);
    uint2 k = *reinterpret_cast<const uint2*>(&g_Kh[(bh * S + i0 + r) * DK + u * 4]);
    Qs[r][u * 2] = q.x;  Qs[r][u * 2 + 1] = q.y;
    Ks2[r][u * 2] = k.x; Ks2[r][u * 2 + 1] = k.y;
  }
  for (int i = tid; i < 48 * 16; i += 256) {
    const int r = i >> 4, cc = (i & 15) * 4;
    const float* sq = (r < TH) ? &qhe[r * HID + h * DK + cc] : &qee[(r - TH) * HID + h * DK + cc];
    const float* sk = (r < TH) ? &khe[r * HID + h * DK + cc] : &kee[(r - TH) * HID + h * DK + cc];
    float4 vq = *reinterpret_cast<const float4*>(sq);
    float4 vk = *reinterpret_cast<const float4*>(sk);
    Eq[r][(cc >> 1)]     = pack_half2(vq.x, vq.y);
    Eq[r][(cc >> 1) + 1] = pack_half2(vq.z, vq.w);
    Ek[r][(cc >> 1)]     = pack_half2(vk.x, vk.y);
    Ek[r][(cc >> 1) + 1] = pack_half2(vk.z, vk.w);
  }
  __syncthreads();

  float cQ[3][4] = {}, cK[3][4] = {};
#pragma unroll
  for (int ks = 0; ks < 4; ks++) {
    const int kw = ks * 8;
    const int rr = wm * 16 + g;
    unsigned aQ[4], aK[4], bQ[3][2], bK[3][2];
    aQ[0] = Qs[rr][kw + t4];      aQ[1] = Qs[rr + 8][kw + t4];
    aQ[2] = Qs[rr][kw + 4 + t4];  aQ[3] = Qs[rr + 8][kw + 4 + t4];
    aK[0] = Ks2[rr][kw + t4];     aK[1] = Ks2[rr + 8][kw + t4];
    aK[2] = Ks2[rr][kw + 4 + t4]; aK[3] = Ks2[rr + 8][kw + 4 + t4];
#pragma unroll
    for (int ni = 0; ni < 3; ni++) {
      const int cc = wn * 24 + ni * 8 + g;
      bQ[ni][0] = Eq[cc][kw + t4]; bQ[ni][1] = Eq[cc][kw + 4 + t4];
      bK[ni][0] = Ek[cc][kw + t4]; bK[ni][1] = Ek[cc][kw + 4 + t4];
    }
#pragma unroll
    for (int ni = 0; ni < 3; ni++) {
      mma_f16(cQ[ni], aQ, bQ[ni]);
      mma_f16(cK[ni], aK, bK[ni]);
    }
  }
#pragma unroll
  for (int ni = 0; ni < 3; ni++)
#pragma unroll
    for (int hf = 0; hf < 2; hf++) {
      const int row = i0 + wm * 16 + g + hf * 8;
      const int col = wn * 24 + ni * 8 + t4 * 2;
      const float q0 = cQ[ni][hf * 2], q1 = cQ[ni][hf * 2 + 1];
      const float k0 = cK[ni][hf * 2], k1 = cK[ni][hf * 2 + 1];
      if (col < TH) {
        *reinterpret_cast<__half2*>(&g_QHop16[(bh * S + row) * TH + col]) =
            __floats2half2_rn(q0, q1);
        *reinterpret_cast<__half2*>(&g_KHop16[(bh * S + row) * TH + col]) =
            __floats2half2_rn(k0, k1);
      } else {
        *reinterpret_cast<__half2*>(&g_EB16[(bh * S + row) * TE + (col - TH)]) =
            __floats2half2_rn(q0 + k0, q1 + k1);
      }
    }
}

// ---------------- fused flash attention + bins ---------------------------------
struct FSmem {
  unsigned Qs[64][36];
  unsigned Ks[128][36];
  unsigned Vt[64][68];       // V^T chunk [d][j]; tables in epilogue
  unsigned Ph[64][68];       // half P; normalized bins in epilogue
  __half KHs[128 * 40];      // flat: row*40 + t
  __half rowhopH[64 * 40];   // flat: row*40 + t
  __half rowedgeH[64 * 24];  // flat: row*24 + t
  float binsH[64][32];
  float binsE[64][16];
  float rowl[64];
  unsigned short de[64][128];
};

__global__ __launch_bounds__(512) void fused_attn(
    const float* __restrict__ vhe, const float* __restrict__ vee) {
  extern __shared__ char smem_raw[];
  FSmem& sm = *reinterpret_cast<FSmem*>(smem_raw);
  const int bh = blockIdx.x, b = bh >> 3, h = bh & 7;
  const int i0 = blockIdx.y * 64;
  const int tid = threadIdx.x;
  const int lane = tid & 31, wid = tid >> 5;
  const int g = lane >> 2, t4 = lane & 3;
  const int wmq = wid & 3, wnq = wid >> 2;  // QK: 16 x 32
  const int wma = wid & 3, wna = wid >> 2;  // AV: 16 x 16

  for (int i = tid; i < 64 * 16; i += 512) {
    const int r = i >> 4, u = i & 15;
    uint2 q = *reinterpret_cast<const uint2*>(&g_Qh[(bh * S + i0 + r) * DK + u * 4]);
    sm.Qs[r][u * 2] = q.x; sm.Qs[r][u * 2 + 1] = q.y;
  }
  for (int i = tid; i < 64 * 4; i += 512) {  // rowhop: 4 x uint4 per row
    const int r = i >> 2, u = (i & 3);
    uint4 v = *reinterpret_cast<const uint4*>(&g_QHop16[(bh * S + i0 + r) * TH + u * 8]);
    *reinterpret_cast<uint4*>(&sm.rowhopH[r * 40 + u * 8]) = v;
  }
  for (int i = tid; i < 64 * 2; i += 512) {  // rowedge: 2 x uint4 per row
    const int r = i >> 1, u = (i & 1);
    uint4 v = *reinterpret_cast<const uint4*>(&g_EB16[(bh * S + i0 + r) * TE + u * 8]);
    *reinterpret_cast<uint4*>(&sm.rowedgeH[r * 24 + u * 8]) = v;
  }
  for (int i = tid; i < 64 * 32; i += 512) sm.binsH[i >> 5][i & 31] = 0.f;
  for (int i = tid; i < 64 * 16; i += 512) sm.binsE[i >> 4][i & 15] = 0.f;
  if (tid < 64) sm.rowl[tid] = 0.f;

  float co[2][4] = {};
  const int rrq = wmq * 16 + g;
  const int rra = wma * 16 + g;

  for (int ch = 0; ch < 4; ch++) {
    const int j0 = ch * 128;
    for (int i = tid; i < 128 * 16; i += 512) {
      const int r = i >> 4, u = i & 15;
      uint2 k = *reinterpret_cast<const uint2*>(&g_Kh[(bh * S + j0 + r) * DK + u * 4]);
      sm.Ks[r][u * 2] = k.x; sm.Ks[r][u * 2 + 1] = k.y;
    }
    for (int i = tid; i < 64 * 32; i += 512) {
      const int d = i >> 5, u = i & 31;
      uint2 v = *reinterpret_cast<const uint2*>(&g_VhT[(size_t)(bh * DK + d) * S + j0 + u * 4]);
      sm.Vt[d][u * 2] = v.x; sm.Vt[d][u * 2 + 1] = v.y;
    }
    for (int i = tid; i < 128 * 4; i += 512) {  // KHop: 4 x uint4 per row
      const int r = i >> 2, u = (i & 3);
      uint4 v = *reinterpret_cast<const uint4*>(&g_KHop16[(bh * S + j0 + r) * TH + u * 8]);
      *reinterpret_cast<uint4*>(&sm.KHs[r * 40 + u * 8]) = v;
    }
    for (int i = tid; i < 64 * 16; i += 512) {
      const int r = i >> 4, c8 = (i & 15) * 8;
      const size_t base = ((size_t)b * S + i0 + r) * S + j0 + c8;
      *reinterpret_cast<uint4*>(&sm.de[r][c8]) =
          *reinterpret_cast<const uint4*>(&g_DE16[base]);
    }
    __syncthreads();

    // ---- QK mma ----
    float cq[4][4] = {};
#pragma unroll
    for (int ks = 0; ks < 4; ks++) {
      const int kw = ks * 8;
      unsigned a[4], bf[4][2];
      a[0] = sm.Qs[rrq][kw + t4];     a[1] = sm.Qs[rrq + 8][kw + t4];
      a[2] = sm.Qs[rrq][kw + 4 + t4]; a[3] = sm.Qs[rrq + 8][kw + 4 + t4];
#pragma unroll
      for (int ni = 0; ni < 4; ni++) {
        const int jl = wnq * 32 + ni * 8 + g;
        bf[ni][0] = sm.Ks[jl][kw + t4]; bf[ni][1] = sm.Ks[jl][kw + 4 + t4];
      }
#pragma unroll
      for (int ni = 0; ni < 4; ni++) mma_f16(cq[ni], a, bf[ni]);
    }

    // ---- fused epilogue: bias gather + exp2 + bins + row sums + P(half2) ----
    {
      const int r0 = rrq, r1 = rrq + 8;
      float s0 = 0.f, s1 = 0.f;
#pragma unroll
      for (int ni = 0; ni < 4; ni++) {
        const int jl = wnq * 32 + ni * 8 + t4 * 2;
        const unsigned de0 = *reinterpret_cast<const unsigned*>(&sm.de[r0][jl]);
        const unsigned de1 = *reinterpret_cast<const unsigned*>(&sm.de[r1][jl]);
        {
          const int dhA = de0 & 0xFF, eeA = (de0 >> 8) & 0xFF;
          const int dhB = (de0 >> 16) & 0xFF, eeB = de0 >> 24;
          const float scA = (cq[ni][0] + __half2float(sm.rowhopH[r0 * 40 + dhA]) +
                             __half2float(sm.KHs[jl * 40 + dhA]) +
                             __half2float(sm.rowedgeH[r0 * 24 + eeA])) * SC2;
          const float scB = (cq[ni][1] + __half2float(sm.rowhopH[r0 * 40 + dhB]) +
                             __half2float(sm.KHs[(jl + 1) * 40 + dhB]) +
                             __half2float(sm.rowedgeH[r0 * 24 + eeB])) * SC2;
          const float pA = fast_exp2(scA), pB = fast_exp2(scB);
          sm.Ph[r0][jl >> 1] = pack_half2(pA, pB);
          atomicAdd(&sm.binsH[r0][dhA], pA); atomicAdd(&sm.binsE[r0][eeA], pA);
          atomicAdd(&sm.binsH[r0][dhB], pB); atomicAdd(&sm.binsE[r0][eeB], pB);
          s0 += pA + pB;
        }
        {
          const int dhA = de1 & 0xFF, eeA = (de1 >> 8) & 0xFF;
          const int dhB = (de1 >> 16) & 0xFF, eeB = de1 >> 24;
          const float scA = (cq[ni][2] + __half2float(sm.rowhopH[r1 * 40 + dhA]) +
                             __half2float(sm.KHs[jl * 40 + dhA]) +
                             __half2float(sm.rowedgeH[r1 * 24 + eeA])) * SC2;
          const float scB = (cq[ni][3] + __half2float(sm.rowhopH[r1 * 40 + dhB]) +
                             __half2float(sm.KHs[(jl + 1) * 40 + dhB]) +
                             __half2float(sm.rowedgeH[r1 * 24 + eeB])) * SC2;
          const float pA = fast_exp2(scA), pB = fast_exp2(scB);
          sm.Ph[r1][jl >> 1] = pack_half2(pA, pB);
          atomicAdd(&sm.binsH[r1][dhA], pA); atomicAdd(&sm.binsE[r1][eeA], pA);
          atomicAdd(&sm.binsH[r1][dhB], pB); atomicAdd(&sm.binsE[r1][eeB], pB);
          s1 += pA + pB;
        }
      }
      // quad-reduce row sums (lanes sharing g share rows)
      s0 += __shfl_xor_sync(0xffffffffu, s0, 1);
      s0 += __shfl_xor_sync(0xffffffffu, s0, 2);
      s1 += __shfl_xor_sync(0xffffffffu, s1, 1);
      s1 += __shfl_xor_sync(0xffffffffu, s1, 2);
      if (t4 == 0) {
        atomicAdd(&sm.rowl[r0], s0);
        atomicAdd(&sm.rowl[r1], s1);
      }
    }
    __syncthreads();

    // ---- P@V mma ----
#pragma unroll
    for (int ks = 0; ks < 8; ks++) {
      const int kw = ks * 8;
      unsigned a[4], bf[2][2];
      a[0] = sm.Ph[rra][kw + t4];     a[1] = sm.Ph[rra + 8][kw + t4];
      a[2] = sm.Ph[rra][kw + 4 + t4]; a[3] = sm.Ph[rra + 8][kw + 4 + t4];
#pragma unroll
      for (int ni = 0; ni < 2; ni++) {
        const int cc = wna * 16 + ni * 8 + g;
        bf[ni][0] = sm.Vt[cc][kw + t4]; bf[ni][1] = sm.Vt[cc][kw + 4 + t4];
      }
#pragma unroll
      for (int ni = 0; ni < 2; ni++) mma_f16(co[ni], a, bf[ni]);
    }
    __syncthreads();
  }

  // ---- epilogue: normalize O, add normalized-bins GEMMs, store ----
  const float inv0 = 1.f / sm.rowl[rra];
  const float inv1 = 1.f / sm.rowl[rra + 8];
#pragma unroll
  for (int ni = 0; ni < 2; ni++) {
    co[ni][0] *= inv0; co[ni][1] *= inv0;
    co[ni][2] *= inv1; co[ni][3] *= inv1;
  }
  for (int i = tid; i < 64 * 48; i += 512) {
    const int r = i / 48, t = i % 48;
    const float invr = 1.f / sm.rowl[r];
    const float v = ((t < TH) ? sm.binsH[r][t] : sm.binsE[r][t - TH]) * invr;
    reinterpret_cast<__half*>(&sm.Ph[r][0])[t] = __float2half_rn(v);
  }
  for (int i = tid; i < 64 * 24; i += 512) {
    const int d = i / 24, tw = i % 24;
    const int t0 = tw * 2, t1 = t0 + 1;
    const float x = (t0 < TH) ? vhe[t0 * HID + h * DK + d] : vee[(t0 - TH) * HID + h * DK + d];
    const float y = (t1 < TH) ? vhe[t1 * HID + h * DK + d] : vee[(t1 - TH) * HID + h * DK + d];
    sm.Vt[d][tw] = pack_half2(x, y);
  }
  __syncthreads();
#pragma unroll
  for (int ks = 0; ks < 3; ks++) {
    const int kw = ks * 8;
    unsigned a[4], bf[2][2];
    a[0] = sm.Ph[rra][kw + t4];     a[1] = sm.Ph[rra + 8][kw + t4];
    a[2] = sm.Ph[rra][kw + 4 + t4]; a[3] = sm.Ph[rra + 8][kw + 4 + t4];
#pragma unroll
    for (int ni = 0; ni < 2; ni++) {
      const int cc = wna * 16 + ni * 8 + g;
      bf[ni][0] = sm.Vt[cc][kw + t4]; bf[ni][1] = sm.Vt[cc][kw + 4 + t4];
    }
#pragma unroll
    for (int ni = 0; ni < 2; ni++) mma_f16(co[ni], a, bf[ni]);
  }

#pragma unroll
  for (int ni = 0; ni < 2; ni++) {
    const int col = wna * 16 + ni * 8 + t4 * 2;
    const int row0 = i0 + wma * 16 + g;
    *reinterpret_cast<__half2*>(&g_OutH[(bh * S + row0) * DK + col]) =
        __floats2half2_rn(co[ni][0], co[ni][1]);
    *reinterpret_cast<__half2*>(&g_OutH[(bh * S + row0 + 8) * DK + col]) =
        __floats2half2_rn(co[ni][2], co[ni][3]);
  }
}

// ---------------- launcher ----------------------------------------------------
extern "C" void kernel_launch(void* const* d_in, const int* in_sizes, int n_in,
                              void* d_out, int out_size) {
  (void)in_sizes; (void)n_in; (void)out_size;
  const float* q   = (const float*)d_in[0];
  const float* k   = (const float*)d_in[1];
  const float* v   = (const float*)d_in[2];
  const float* qhe = (const float*)d_in[3];
  const float* qee = (const float*)d_in[4];
  const float* khe = (const float*)d_in[5];
  const float* kee = (const float*)d_in[6];
  const float* vhe = (const float*)d_in[7];
  const float* vee = (const float*)d_in[8];
  const int* dist  = (const int*)d_in[9];
  const int* edge  = (const int*)d_in[10];
  const float* Wq = (const float*)d_in[11], *bq = (const float*)d_in[12];
  const float* Wk = (const float*)d_in[13], *bk = (const float*)d_in[14];
  const float* Wv = (const float*)d_in[15], *bv = (const float*)d_in[16];
  const float* Wo = (const float*)d_in[17], *bo = (const float*)d_in[18];
  float* out = (float*)d_out;

  const int proj_smem = (2 * 128 * 72 + 2 * 64 * 72) * 2;  // 55296
  const int fused_smem = (int)sizeof(FSmem);
  cudaFuncSetAttribute(proj_mma<0>, cudaFuncAttributeMaxDynamicSharedMemorySize, proj_smem);
  cudaFuncSetAttribute(proj_mma<1>, cudaFuncAttributeMaxDynamicSharedMemorySize, proj_smem);
  cudaFuncSetAttribute(fused_attn, cudaFuncAttributeMaxDynamicSharedMemorySize, fused_smem);

  const int QU = QN / 8, WU = WN / 8;
  const int prep_total = 3 * QU + 4 * WU + B * S * S / 4;
  prep_kernel<<<(prep_total + 255) / 256, 256>>>(q, k, v, Wq, Wk, Wv, Wo, dist, edge);

  proj_mma<0><<<dim3(8, 64, 3), 256, proj_smem>>>(bq, bk, bv, nullptr);
  tables_mma<<<dim3(BH, 8), 256>>>(qhe, qee, khe, kee);
  fused_attn<<<dim3(BH, 8), 512, fused_smem>>>(vhe, vee);
  proj_mma<1><<<dim3(8, 64, 1), 256, proj_smem>>>(bo, nullptr, nullptr, out);
}

// round 8
// speedup vs baseline: 1.2556x; 1.2556x over previous
#include <cuda_runtime.h>
#include <cuda_fp16.h>

namespace {
constexpr int B = 16, S = 512, HID = 512, NH = 8, DK = 64, TH = 32, TE = 16;
constexpr int BH = 128;
constexpr float SC2 = 0.125f * 1.44269504088896f;  // scale * log2(e)
constexpr int QN = 8192 * 512;
constexpr int WN = 512 * 512;
}

// ---------------- scratch (device globals; no runtime allocation) -------------
__device__ __half g_In16[3][QN];                     // q,k,v as half
__device__ __half g_W16[4][WN];                      // Wq,Wk,Wv,Wo as half
__device__ __half g_Qh[BH * S * DK];
__device__ __half g_Kh[BH * S * DK];
__device__ __half g_VhT[BH * DK * S];                // V transposed: [bh][d][s]
__device__ __half g_QHop16[BH * S * TH];
__device__ __half g_KHop16[BH * S * TH];
__device__ __half g_EB16[BH * S * TE];
__device__ __half g_OutH[BH * S * DK];
__device__ unsigned short g_DE16[(size_t)B * S * S];

// ---------------- helpers -----------------------------------------------------
__device__ __forceinline__ unsigned pack_half2(float x, float y) {
  __half2 h = __floats2half2_rn(x, y);
  return *reinterpret_cast<unsigned*>(&h);
}
__device__ __forceinline__ float fast_exp2(float x) {
  asm("ex2.approx.f32 %0, %0;" : "+f"(x));
  return x;
}
__device__ __forceinline__ void mma_f16(float* c, const unsigned* a, const unsigned* b) {
  asm volatile(
      "mma.sync.aligned.m16n8k16.row.col.f32.f16.f16.f32 "
      "{%0,%1,%2,%3}, {%4,%5,%6,%7}, {%8,%9}, {%0,%1,%2,%3};\n"
      : "+f"(c[0]), "+f"(c[1]), "+f"(c[2]), "+f"(c[3])
      : "r"(a[0]), "r"(a[1]), "r"(a[2]), "r"(a[3]), "r"(b[0]), "r"(b[1]));
}
__device__ __forceinline__ void cpa16(void* sm, const void* gm) {
  unsigned s = (unsigned)__cvta_generic_to_shared(sm);
  asm volatile("cp.async.ca.shared.global [%0], [%1], 16;\n" :: "r"(s), "l"(gm));
}
__device__ __forceinline__ void cp_commit() { asm volatile("cp.async.commit_group;\n"); }
__device__ __forceinline__ void cp_wait1() { asm volatile("cp.async.wait_group 1;\n"); }
__device__ __forceinline__ void cp_wait0() { asm volatile("cp.async.wait_group 0;\n"); }

// ---------------- fused convert (f32->half) + pack (dist|edge -> u16) ---------
__global__ __launch_bounds__(256) void prep_kernel(
    const float* __restrict__ q, const float* __restrict__ k, const float* __restrict__ v,
    const float* __restrict__ Wq, const float* __restrict__ Wk,
    const float* __restrict__ Wv, const float* __restrict__ Wo,
    const int* __restrict__ dist, const int* __restrict__ edge) {
  const int QU = QN / 8, WU = WN / 8;
  const int cv_total = 3 * QU + 4 * WU;
  const int n4 = B * S * S / 4;
  int i = blockIdx.x * 256 + threadIdx.x;
  if (i < cv_total) {
    const float* src; __half* dst; int off;
    if (i < 3 * QU) {
      int z = i / QU; off = (i - z * QU) * 8;
      src = (z == 0) ? q : (z == 1) ? k : v;
      dst = g_In16[z];
    } else {
      int j = i - 3 * QU; int z = j / WU; off = (j - z * WU) * 8;
      src = (z == 0) ? Wq : (z == 1) ? Wk : (z == 2) ? Wv : Wo;
      dst = g_W16[z];
    }
    float4 a = *reinterpret_cast<const float4*>(src + off);
    float4 b2 = *reinterpret_cast<const float4*>(src + off + 4);
    uint4 o;
    o.x = pack_half2(a.x, a.y);  o.y = pack_half2(a.z, a.w);
    o.z = pack_half2(b2.x, b2.y); o.w = pack_half2(b2.z, b2.w);
    *reinterpret_cast<uint4*>(dst + off) = o;
  } else {
    int j = i - cv_total;
    if (j >= n4) return;
    int4 d = reinterpret_cast<const int4*>(dist)[j];
    int4 e = reinterpret_cast<const int4*>(edge)[j];
    ushort4 o;
    o.x = (unsigned short)(d.x | (e.x << 8));
    o.y = (unsigned short)(d.y | (e.y << 8));
    o.z = (unsigned short)(d.z | (e.z << 8));
    o.w = (unsigned short)(d.w | (e.w << 8));
    reinterpret_cast<ushort4*>(g_DE16)[j] = o;
  }
}

// ---------------- proj GEMM (double-buffered cp.async, fp16 mma) --------------
// MODE 0: z=blockIdx.z in {0,1,2} -> Qh/Kh/VhT.  MODE 1: out proj (f32 out).
template <int MODE>
__global__ __launch_bounds__(256) void proj_mma(
    const float* __restrict__ bias0, const float* __restrict__ bias1,
    const float* __restrict__ bias2, float* __restrict__ Cout) {
  extern __shared__ __half psm[];
  __half* Abuf[2] = { psm, psm + 128 * 72 };
  __half* Wbuf[2] = { psm + 2 * 128 * 72, psm + 2 * 128 * 72 + 64 * 72 };
  const int z = (MODE == 0) ? blockIdx.z : 3;
  const __half* A = (MODE == 0) ? g_In16[z] : g_OutH;
  const __half* W = g_W16[z];
  const float* bias = (MODE == 0) ? (z == 0 ? bias0 : (z == 1 ? bias1 : bias2)) : bias0;
  const int m0 = blockIdx.y * 128, n0 = blockIdx.x * 64;
  const int tid = threadIdx.x, lane = tid & 31, wid = tid >> 5;
  const int wm = wid & 3, wn = wid >> 2, g = lane >> 2, t4 = lane & 3;
  const int bbM = m0 >> 9, ii0 = m0 & 511;
  float c[2][4][4] = {};

  auto issue = [&](int s, int buf) {
#pragma unroll
    for (int i = 0; i < 4; i++) {
      int idx = tid + i * 256;
      int r = idx >> 3, c8 = (idx & 7) * 8;
      const __half* gp;
      if (MODE == 0) gp = A + (m0 + r) * 512 + s * 64 + c8;
      else {
        int n = m0 + r, bb = n >> 9, ii = n & 511;
        gp = g_OutH + ((bb * NH + s) * S + ii) * DK + c8;
      }
      cpa16(Abuf[buf] + r * 72 + c8, gp);
    }
#pragma unroll
    for (int i = 0; i < 2; i++) {
      int idx = tid + i * 256;
      int r = idx >> 3, c8 = (idx & 7) * 8;
      cpa16(Wbuf[buf] + r * 72 + c8, W + (n0 + r) * 512 + s * 64 + c8);
    }
    cp_commit();
  };

  issue(0, 0);
  for (int s = 0; s < 8; s++) {
    const int buf = s & 1;
    if (s < 7) { issue(s + 1, buf ^ 1); cp_wait1(); } else { cp_wait0(); }
    __syncthreads();
    const unsigned* Ar = reinterpret_cast<const unsigned*>(Abuf[buf]);
    const unsigned* Wr = reinterpret_cast<const unsigned*>(Wbuf[buf]);
#pragma unroll
    for (int k16 = 0; k16 < 4; k16++) {
      const int kw = k16 * 8;
      unsigned a[2][4], b[4][2];
#pragma unroll
      for (int mi = 0; mi < 2; mi++) {
        const int rr = wm * 32 + mi * 16 + g;
        a[mi][0] = Ar[rr * 36 + kw + t4];       a[mi][1] = Ar[(rr + 8) * 36 + kw + t4];
        a[mi][2] = Ar[rr * 36 + kw + 4 + t4];   a[mi][3] = Ar[(rr + 8) * 36 + kw + 4 + t4];
      }
#pragma unroll
      for (int ni = 0; ni < 4; ni++) {
        const int cc = wn * 32 + ni * 8 + g;
        b[ni][0] = Wr[cc * 36 + kw + t4]; b[ni][1] = Wr[cc * 36 + kw + 4 + t4];
      }
#pragma unroll
      for (int mi = 0; mi < 2; mi++)
#pragma unroll
        for (int ni = 0; ni < 4; ni++) mma_f16(c[mi][ni], a[mi], b[ni]);
    }
    __syncthreads();
  }

  if (MODE == 0 && z == 2) {
    __half* Vst = psm;  // [64][136]
#pragma unroll
    for (int mi = 0; mi < 2; mi++)
#pragma unroll
      for (int ni = 0; ni < 4; ni++)
#pragma unroll
        for (int hf = 0; hf < 2; hf++) {
          const int rl = wm * 32 + mi * 16 + g + hf * 8;
          const int d = wn * 32 + ni * 8 + t4 * 2;
          Vst[d * 136 + rl]       = __float2half_rn(c[mi][ni][hf * 2 + 0] + bias[n0 + d]);
          Vst[(d + 1) * 136 + rl] = __float2half_rn(c[mi][ni][hf * 2 + 1] + bias[n0 + d + 1]);
        }
    __syncthreads();
    const int d = tid >> 2, q32 = tid & 3;
    const uint4* srcp = reinterpret_cast<const uint4*>(Vst + d * 136 + q32 * 32);
    __half* dstp = g_VhT + (size_t)((bbM * NH + (n0 >> 6)) * DK + d) * S + ii0 + q32 * 32;
#pragma unroll
    for (int i = 0; i < 4; i++) reinterpret_cast<uint4*>(dstp)[i] = srcp[i];
    return;
  }

#pragma unroll
  for (int mi = 0; mi < 2; mi++)
#pragma unroll
    for (int ni = 0; ni < 4; ni++)
#pragma unroll
      for (int hf = 0; hf < 2; hf++) {
        const int row = m0 + wm * 32 + mi * 16 + g + hf * 8;
        const int col = n0 + wn * 32 + ni * 8 + t4 * 2;
        const float v0 = c[mi][ni][hf * 2 + 0] + bias[col];
        const float v1 = c[mi][ni][hf * 2 + 1] + bias[col + 1];
        if (MODE == 1) {
          *reinterpret_cast<float2*>(&Cout[row * 512 + col]) = make_float2(v0, v1);
        } else {
          const int bb = row >> 9, ii = row & 511, h = col >> 6, d = col & 63;
          __half* dst = (z == 0) ? g_Qh : g_Kh;
          *reinterpret_cast<__half2*>(&dst[(((bb * NH + h) * S) + ii) * DK + d]) =
              __floats2half2_rn(v0, v1);
        }
      }
}

// ---------------- tables: QHop/KHop/EB via fp16 mma (half outputs) ------------
__global__ __launch_bounds__(256) void tables_mma(
    const float* __restrict__ qhe, const float* __restrict__ qee,
    const float* __restrict__ khe, const float* __restrict__ kee) {
  __shared__ unsigned Qs[64][36];
  __shared__ unsigned Ks2[64][36];
  __shared__ unsigned Eq[48][36];
  __shared__ unsigned Ek[48][36];
  const int bh = blockIdx.x, h = bh & 7;
  const int i0 = blockIdx.y * 64;
  const int tid = threadIdx.x;
  const int lane = tid & 31, wid = tid >> 5;
  const int wm = wid & 3, wn = wid >> 2;
  const int g = lane >> 2, t4 = lane & 3;

  for (int i = tid; i < 64 * 16; i += 256) {
    const int r = i >> 4, u = i & 15;
    uint2 q = *reinterpret_cast<const uint2*>(&g_Qh[(bh * S + i0 + r) * DK + u * 4]);
    uint2 k = *reinterpret_cast<const uint2*>(&g_Kh[(bh * S + i0 + r) * DK + u * 4]);
    Qs[r][u * 2] = q.x;  Qs[r][u * 2 + 1] = q.y;
    Ks2[r][u * 2] = k.x; Ks2[r][u * 2 + 1] = k.y;
  }
  for (int i = tid; i < 48 * 16; i += 256) {
    const int r = i >> 4, cc = (i & 15) * 4;
    const float* sq = (r < TH) ? &qhe[r * HID + h * DK + cc] : &qee[(r - TH) * HID + h * DK + cc];
    const float* sk = (r < TH) ? &khe[r * HID + h * DK + cc] : &kee[(r - TH) * HID + h * DK + cc];
    float4 vq = *reinterpret_cast<const float4*>(sq);
    float4 vk = *reinterpret_cast<const float4*>(sk);
    Eq[r][(cc >> 1)]     = pack_half2(vq.x, vq.y);
    Eq[r][(cc >> 1) + 1] = pack_half2(vq.z, vq.w);
    Ek[r][(cc >> 1)]     = pack_half2(vk.x, vk.y);
    Ek[r][(cc >> 1) + 1] = pack_half2(vk.z, vk.w);
  }
  __syncthreads();

  float cQ[3][4] = {}, cK[3][4] = {};
#pragma unroll
  for (int ks = 0; ks < 4; ks++) {
    const int kw = ks * 8;
    const int rr = wm * 16 + g;
    unsigned aQ[4], aK[4], bQ[3][2], bK[3][2];
    aQ[0] = Qs[rr][kw + t4];      aQ[1] = Qs[rr + 8][kw + t4];
    aQ[2] = Qs[rr][kw + 4 + t4];  aQ[3] = Qs[rr + 8][kw + 4 + t4];
    aK[0] = Ks2[rr][kw + t4];     aK[1] = Ks2[rr + 8][kw + t4];
    aK[2] = Ks2[rr][kw + 4 + t4]; aK[3] = Ks2[rr + 8][kw + 4 + t4];
#pragma unroll
    for (int ni = 0; ni < 3; ni++) {
      const int cc = wn * 24 + ni * 8 + g;
      bQ[ni][0] = Eq[cc][kw + t4]; bQ[ni][1] = Eq[cc][kw + 4 + t4];
      bK[ni][0] = Ek[cc][kw + t4]; bK[ni][1] = Ek[cc][kw + 4 + t4];
    }
#pragma unroll
    for (int ni = 0; ni < 3; ni++) {
      mma_f16(cQ[ni], aQ, bQ[ni]);
      mma_f16(cK[ni], aK, bK[ni]);
    }
  }
#pragma unroll
  for (int ni = 0; ni < 3; ni++)
#pragma unroll
    for (int hf = 0; hf < 2; hf++) {
      const int row = i0 + wm * 16 + g + hf * 8;
      const int col = wn * 24 + ni * 8 + t4 * 2;
      const float q0 = cQ[ni][hf * 2], q1 = cQ[ni][hf * 2 + 1];
      const float k0 = cK[ni][hf * 2], k1 = cK[ni][hf * 2 + 1];
      if (col < TH) {
        *reinterpret_cast<__half2*>(&g_QHop16[(bh * S + row) * TH + col]) =
            __floats2half2_rn(q0, q1);
        *reinterpret_cast<__half2*>(&g_KHop16[(bh * S + row) * TH + col]) =
            __floats2half2_rn(k0, k1);
      } else {
        *reinterpret_cast<__half2*>(&g_EB16[(bh * S + row) * TE + (col - TH)]) =
            __floats2half2_rn(q0 + k0, q1 + k1);
      }
    }
}

// ---------------- fused flash attention + bins ---------------------------------
// f32 gather tables at odd strides (full 32-bank randomization); de read from L1.
struct FSmem {
  unsigned Qs[64][36];
  unsigned Ks[128][36];
  unsigned Vt[64][68];       // V^T chunk [d][j]; tables in epilogue
  unsigned Ph[64][68];       // half P; normalized bins in epilogue
  float KHs[128][33];
  float rowhop[64][33];
  float rowedge[64][17];
  float binsH[64][33];
  float binsE[64][17];
  float rowl[64];
};

__global__ __launch_bounds__(512) void fused_attn(
    const float* __restrict__ vhe, const float* __restrict__ vee) {
  extern __shared__ char smem_raw[];
  FSmem& sm = *reinterpret_cast<FSmem*>(smem_raw);
  const int bh = blockIdx.x, b = bh >> 3, h = bh & 7;
  const int i0 = blockIdx.y * 64;
  const int tid = threadIdx.x;
  const int lane = tid & 31, wid = tid >> 5;
  const int g = lane >> 2, t4 = lane & 3;
  const int wmq = wid & 3, wnq = wid >> 2;  // QK: 16 x 32
  const int wma = wid & 3, wna = wid >> 2;  // AV: 16 x 16

  for (int i = tid; i < 64 * 16; i += 512) {
    const int r = i >> 4, u = i & 15;
    uint2 q = *reinterpret_cast<const uint2*>(&g_Qh[(bh * S + i0 + r) * DK + u * 4]);
    sm.Qs[r][u * 2] = q.x; sm.Qs[r][u * 2 + 1] = q.y;
  }
  for (int i = tid; i < 64 * 8; i += 512) {  // rowhop: 8 x (4 halves) per row
    const int r = i >> 3, u = i & 7;
    uint2 v = *reinterpret_cast<const uint2*>(&g_QHop16[(bh * S + i0 + r) * TH + u * 4]);
    __half2 h0 = *reinterpret_cast<__half2*>(&v.x);
    __half2 h1 = *reinterpret_cast<__half2*>(&v.y);
    sm.rowhop[r][u * 4 + 0] = __low2float(h0);
    sm.rowhop[r][u * 4 + 1] = __high2float(h0);
    sm.rowhop[r][u * 4 + 2] = __low2float(h1);
    sm.rowhop[r][u * 4 + 3] = __high2float(h1);
  }
  for (int i = tid; i < 64 * 4; i += 512) {  // rowedge: 4 x (4 halves) per row
    const int r = i >> 2, u = i & 3;
    uint2 v = *reinterpret_cast<const uint2*>(&g_EB16[(bh * S + i0 + r) * TE + u * 4]);
    __half2 h0 = *reinterpret_cast<__half2*>(&v.x);
    __half2 h1 = *reinterpret_cast<__half2*>(&v.y);
    sm.rowedge[r][u * 4 + 0] = __low2float(h0);
    sm.rowedge[r][u * 4 + 1] = __high2float(h0);
    sm.rowedge[r][u * 4 + 2] = __low2float(h1);
    sm.rowedge[r][u * 4 + 3] = __high2float(h1);
  }
  for (int i = tid; i < 64 * 33; i += 512) sm.binsH[i / 33][i % 33] = 0.f;
  for (int i = tid; i < 64 * 17; i += 512) sm.binsE[i / 17][i % 17] = 0.f;
  if (tid < 64) sm.rowl[tid] = 0.f;

  float co[2][4] = {};
  const int rrq = wmq * 16 + g;
  const int rra = wma * 16 + g;

  for (int ch = 0; ch < 4; ch++) {
    const int j0 = ch * 128;
    for (int i = tid; i < 128 * 16; i += 512) {
      const int r = i >> 4, u = i & 15;
      uint2 k = *reinterpret_cast<const uint2*>(&g_Kh[(bh * S + j0 + r) * DK + u * 4]);
      sm.Ks[r][u * 2] = k.x; sm.Ks[r][u * 2 + 1] = k.y;
    }
    for (int i = tid; i < 64 * 32; i += 512) {
      const int d = i >> 5, u = i & 31;
      uint2 v = *reinterpret_cast<const uint2*>(&g_VhT[(size_t)(bh * DK + d) * S + j0 + u * 4]);
      sm.Vt[d][u * 2] = v.x; sm.Vt[d][u * 2 + 1] = v.y;
    }
    for (int i = tid; i < 128 * 8; i += 512) {  // KHop: 8 x (4 halves) per row -> f32
      const int r = i >> 3, u = i & 7;
      uint2 v = *reinterpret_cast<const uint2*>(&g_KHop16[(bh * S + j0 + r) * TH + u * 4]);
      __half2 h0 = *reinterpret_cast<__half2*>(&v.x);
      __half2 h1 = *reinterpret_cast<__half2*>(&v.y);
      sm.KHs[r][u * 4 + 0] = __low2float(h0);
      sm.KHs[r][u * 4 + 1] = __high2float(h0);
      sm.KHs[r][u * 4 + 2] = __low2float(h1);
      sm.KHs[r][u * 4 + 3] = __high2float(h1);
    }
    __syncthreads();

    // ---- QK mma ----
    float cq[4][4] = {};
#pragma unroll
    for (int ks = 0; ks < 4; ks++) {
      const int kw = ks * 8;
      unsigned a[4], bf[4][2];
      a[0] = sm.Qs[rrq][kw + t4];     a[1] = sm.Qs[rrq + 8][kw + t4];
      a[2] = sm.Qs[rrq][kw + 4 + t4]; a[3] = sm.Qs[rrq + 8][kw + 4 + t4];
#pragma unroll
      for (int ni = 0; ni < 4; ni++) {
        const int jl = wnq * 32 + ni * 8 + g;
        bf[ni][0] = sm.Ks[jl][kw + t4]; bf[ni][1] = sm.Ks[jl][kw + 4 + t4];
      }
#pragma unroll
      for (int ni = 0; ni < 4; ni++) mma_f16(cq[ni], a, bf[ni]);
    }

    // ---- fused epilogue: de from L1, bias gather + exp2 + bins + sums ----
    {
      const int r0 = rrq, r1 = rrq + 8;
      const size_t deb0 = ((size_t)b * S + i0 + r0) * S + j0;
      const size_t deb1 = ((size_t)b * S + i0 + r1) * S + j0;
      float s0 = 0.f, s1 = 0.f;
#pragma unroll
      for (int ni = 0; ni < 4; ni++) {
        const int jl = wnq * 32 + ni * 8 + t4 * 2;
        const unsigned de0 = *reinterpret_cast<const unsigned*>(&g_DE16[deb0 + jl]);
        const unsigned de1 = *reinterpret_cast<const unsigned*>(&g_DE16[deb1 + jl]);
        {
          const int dhA = de0 & 0xFF, eeA = (de0 >> 8) & 0xFF;
          const int dhB = (de0 >> 16) & 0xFF, eeB = de0 >> 24;
          const float scA = (cq[ni][0] + sm.rowhop[r0][dhA] + sm.KHs[jl][dhA] +
                             sm.rowedge[r0][eeA]) * SC2;
          const float scB = (cq[ni][1] + sm.rowhop[r0][dhB] + sm.KHs[jl + 1][dhB] +
                             sm.rowedge[r0][eeB]) * SC2;
          const float pA = fast_exp2(scA), pB = fast_exp2(scB);
          sm.Ph[r0][jl >> 1] = pack_half2(pA, pB);
          atomicAdd(&sm.binsH[r0][dhA], pA); atomicAdd(&sm.binsE[r0][eeA], pA);
          atomicAdd(&sm.binsH[r0][dhB], pB); atomicAdd(&sm.binsE[r0][eeB], pB);
          s0 += pA + pB;
        }
        {
          const int dhA = de1 & 0xFF, eeA = (de1 >> 8) & 0xFF;
          const int dhB = (de1 >> 16) & 0xFF, eeB = de1 >> 24;
          const float scA = (cq[ni][2] + sm.rowhop[r1][dhA] + sm.KHs[jl][dhA] +
                             sm.rowedge[r1][eeA]) * SC2;
          const float scB = (cq[ni][3] + sm.rowhop[r1][dhB] + sm.KHs[jl + 1][dhB] +
                             sm.rowedge[r1][eeB]) * SC2;
          const float pA = fast_exp2(scA), pB = fast_exp2(scB);
          sm.Ph[r1][jl >> 1] = pack_half2(pA, pB);
          atomicAdd(&sm.binsH[r1][dhA], pA); atomicAdd(&sm.binsE[r1][eeA], pA);
          atomicAdd(&sm.binsH[r1][dhB], pB); atomicAdd(&sm.binsE[r1][eeB], pB);
          s1 += pA + pB;
        }
      }
      // quad-reduce row sums (lanes sharing g share rows)
      s0 += __shfl_xor_sync(0xffffffffu, s0, 1);
      s0 += __shfl_xor_sync(0xffffffffu, s0, 2);
      s1 += __shfl_xor_sync(0xffffffffu, s1, 1);
      s1 += __shfl_xor_sync(0xffffffffu, s1, 2);
      if (t4 == 0) {
        atomicAdd(&sm.rowl[r0], s0);
        atomicAdd(&sm.rowl[r1], s1);
      }
    }
    __syncthreads();

    // ---- P@V mma ----
#pragma unroll
    for (int ks = 0; ks < 8; ks++) {
      const int kw = ks * 8;
      unsigned a[4], bf[2][2];
      a[0] = sm.Ph[rra][kw + t4];     a[1] = sm.Ph[rra + 8][kw + t4];
      a[2] = sm.Ph[rra][kw + 4 + t4]; a[3] = sm.Ph[rra + 8][kw + 4 + t4];
#pragma unroll
      for (int ni = 0; ni < 2; ni++) {
        const int cc = wna * 16 + ni * 8 + g;
        bf[ni][0] = sm.Vt[cc][kw + t4]; bf[ni][1] = sm.Vt[cc][kw + 4 + t4];
      }
#pragma unroll
      for (int ni = 0; ni < 2; ni++) mma_f16(co[ni], a, bf[ni]);
    }
    __syncthreads();
  }

  // ---- epilogue: normalize O, add normalized-bins GEMMs, store ----
  const float inv0 = 1.f / sm.rowl[rra];
  const float inv1 = 1.f / sm.rowl[rra + 8];
#pragma unroll
  for (int ni = 0; ni < 2; ni++) {
    co[ni][0] *= inv0; co[ni][1] *= inv0;
    co[ni][2] *= inv1; co[ni][3] *= inv1;
  }
  for (int i = tid; i < 64 * 48; i += 512) {
    const int r = i / 48, t = i % 48;
    const float invr = 1.f / sm.rowl[r];
    const float v = ((t < TH) ? sm.binsH[r][t] : sm.binsE[r][t - TH]) * invr;
    reinterpret_cast<__half*>(&sm.Ph[r][0])[t] = __float2half_rn(v);
  }
  for (int i = tid; i < 64 * 24; i += 512) {
    const int d = i / 24, tw = i % 24;
    const int t0 = tw * 2, t1 = t0 + 1;
    const float x = (t0 < TH) ? vhe[t0 * HID + h * DK + d] : vee[(t0 - TH) * HID + h * DK + d];
    const float y = (t1 < TH) ? vhe[t1 * HID + h * DK + d] : vee[(t1 - TH) * HID + h * DK + d];
    sm.Vt[d][tw] = pack_half2(x, y);
  }
  __syncthreads();
#pragma unroll
  for (int ks = 0; ks < 3; ks++) {
    const int kw = ks * 8;
    unsigned a[4], bf[2][2];
    a[0] = sm.Ph[rra][kw + t4];     a[1] = sm.Ph[rra + 8][kw + t4];
    a[2] = sm.Ph[rra][kw + 4 + t4]; a[3] = sm.Ph[rra + 8][kw + 4 + t4];
#pragma unroll
    for (int ni = 0; ni < 2; ni++) {
      const int cc = wna * 16 + ni * 8 + g;
      bf[ni][0] = sm.Vt[cc][kw + t4]; bf[ni][1] = sm.Vt[cc][kw + 4 + t4];
    }
#pragma unroll
    for (int ni = 0; ni < 2; ni++) mma_f16(co[ni], a, bf[ni]);
  }

#pragma unroll
  for (int ni = 0; ni < 2; ni++) {
    const int col = wna * 16 + ni * 8 + t4 * 2;
    const int row0 = i0 + wma * 16 + g;
    *reinterpret_cast<__half2*>(&g_OutH[(bh * S + row0) * DK + col]) =
        __floats2half2_rn(co[ni][0], co[ni][1]);
    *reinterpret_cast<__half2*>(&g_OutH[(bh * S + row0 + 8) * DK + col]) =
        __floats2half2_rn(co[ni][2], co[ni][3]);
  }
}

// ---------------- launcher ----------------------------------------------------
extern "C" void kernel_launch(void* const* d_in, const int* in_sizes, int n_in,
                              void* d_out, int out_size) {
  (void)in_sizes; (void)n_in; (void)out_size;
  const float* q   = (const float*)d_in[0];
  const float* k   = (const float*)d_in[1];
  const float* v   = (const float*)d_in[2];
  const float* qhe = (const float*)d_in[3];
  const float* qee = (const float*)d_in[4];
  const float* khe = (const float*)d_in[5];
  const float* kee = (const float*)d_in[6];
  const float* vhe = (const float*)d_in[7];
  const float* vee = (const float*)d_in[8];
  const int* dist  = (const int*)d_in[9];
  const int* edge  = (const int*)d_in[10];
  const float* Wq = (const float*)d_in[11], *bq = (const float*)d_in[12];
  const float* Wk = (const float*)d_in[13], *bk = (const float*)d_in[14];
  const float* Wv = (const float*)d_in[15], *bv = (const float*)d_in[16];
  const float* Wo = (const float*)d_in[17], *bo = (const float*)d_in[18];
  float* out = (float*)d_out;

  const int proj_smem = (2 * 128 * 72 + 2 * 64 * 72) * 2;  // 55296
  const int fused_smem = (int)sizeof(FSmem);                // ~105 KB -> 2 CTA/SM
  cudaFuncSetAttribute(proj_mma<0>, cudaFuncAttributeMaxDynamicSharedMemorySize, proj_smem);
  cudaFuncSetAttribute(proj_mma<1>, cudaFuncAttributeMaxDynamicSharedMemorySize, proj_smem);
  cudaFuncSetAttribute(fused_attn, cudaFuncAttributeMaxDynamicSharedMemorySize, fused_smem);

  const int QU = QN / 8, WU = WN / 8;
  const int prep_total = 3 * QU + 4 * WU + B * S * S / 4;
  prep_kernel<<<(prep_total + 255) / 256, 256>>>(q, k, v, Wq, Wk, Wv, Wo, dist, edge);

  proj_mma<0><<<dim3(8, 64, 3), 256, proj_smem>>>(bq, bk, bv, nullptr);
  tables_mma<<<dim3(BH, 8), 256>>>(qhe, qee, khe, kee);
  fused_attn<<<dim3(BH, 8), 512, fused_smem>>>(vhe, vee);
  proj_mma<1><<<dim3(8, 64, 1), 256, proj_smem>>>(bo, nullptr, nullptr, out);
}

// round 9
// speedup vs baseline: 1.3828x; 1.1012x over previous
#include <cuda_runtime.h>
#include <cuda_fp16.h>

namespace {
constexpr int B = 16, S = 512, HID = 512, NH = 8, DK = 64, TH = 32, TE = 16;
constexpr int BH = 128;
constexpr float SC2 = 0.125f * 1.44269504088896f;  // scale * log2(e)
constexpr int QN = 8192 * 512;
constexpr int WN = 512 * 512;
}

// ---------------- scratch (device globals; no runtime allocation) -------------
__device__ __half g_In16[3][QN];                     // q,k,v as half
__device__ __half g_W16[4][WN];                      // Wq,Wk,Wv,Wo as half
__device__ __half g_Qh[BH * S * DK];
__device__ __half g_Kh[BH * S * DK];
__device__ __half g_VhT[BH * DK * S];                // V transposed: [bh][d][s]
__device__ __half g_QHop16[BH * S * TH];
__device__ float  g_KHop32[BH * S * TH];
__device__ __half g_EB16[BH * S * TE];
__device__ __half g_OutH[BH * S * DK];
__device__ unsigned short g_DE16[(size_t)B * S * S];

// ---------------- helpers -----------------------------------------------------
__device__ __forceinline__ unsigned pack_half2(float x, float y) {
  __half2 h = __floats2half2_rn(x, y);
  return *reinterpret_cast<unsigned*>(&h);
}
__device__ __forceinline__ float fast_exp2(float x) {
  asm("ex2.approx.f32 %0, %0;" : "+f"(x));
  return x;
}
__device__ __forceinline__ void mma_f16(float* c, const unsigned* a, const unsigned* b) {
  asm volatile(
      "mma.sync.aligned.m16n8k16.row.col.f32.f16.f16.f32 "
      "{%0,%1,%2,%3}, {%4,%5,%6,%7}, {%8,%9}, {%0,%1,%2,%3};\n"
      : "+f"(c[0]), "+f"(c[1]), "+f"(c[2]), "+f"(c[3])
      : "r"(a[0]), "r"(a[1]), "r"(a[2]), "r"(a[3]), "r"(b[0]), "r"(b[1]));
}
__device__ __forceinline__ void ldsm_x4(unsigned* r, unsigned saddr) {
  asm volatile("ldmatrix.sync.aligned.m8n8.x4.shared.b16 {%0,%1,%2,%3}, [%4];"
               : "=r"(r[0]), "=r"(r[1]), "=r"(r[2]), "=r"(r[3]) : "r"(saddr));
}
__device__ __forceinline__ void cpa16(void* sm, const void* gm) {
  unsigned s = (unsigned)__cvta_generic_to_shared(sm);
  asm volatile("cp.async.ca.shared.global [%0], [%1], 16;\n" :: "r"(s), "l"(gm));
}
__device__ __forceinline__ void cp_commit() { asm volatile("cp.async.commit_group;\n"); }
__device__ __forceinline__ void cp_wait1() { asm volatile("cp.async.wait_group 1;\n"); }
__device__ __forceinline__ void cp_wait0() { asm volatile("cp.async.wait_group 0;\n"); }

// ---------------- fused convert (f32->half) + pack (dist|edge -> u16) ---------
__global__ __launch_bounds__(256) void prep_kernel(
    const float* __restrict__ q, const float* __restrict__ k, const float* __restrict__ v,
    const float* __restrict__ Wq, const float* __restrict__ Wk,
    const float* __restrict__ Wv, const float* __restrict__ Wo,
    const int* __restrict__ dist, const int* __restrict__ edge) {
  const int QU = QN / 8, WU = WN / 8;
  const int cv_total = 3 * QU + 4 * WU;
  const int n4 = B * S * S / 4;
  int i = blockIdx.x * 256 + threadIdx.x;
  if (i < cv_total) {
    const float* src; __half* dst; int off;
    if (i < 3 * QU) {
      int z = i / QU; off = (i - z * QU) * 8;
      src = (z == 0) ? q : (z == 1) ? k : v;
      dst = g_In16[z];
    } else {
      int j = i - 3 * QU; int z = j / WU; off = (j - z * WU) * 8;
      src = (z == 0) ? Wq : (z == 1) ? Wk : (z == 2) ? Wv : Wo;
      dst = g_W16[z];
    }
    float4 a = *reinterpret_cast<const float4*>(src + off);
    float4 b2 = *reinterpret_cast<const float4*>(src + off + 4);
    uint4 o;
    o.x = pack_half2(a.x, a.y);  o.y = pack_half2(a.z, a.w);
    o.z = pack_half2(b2.x, b2.y); o.w = pack_half2(b2.z, b2.w);
    *reinterpret_cast<uint4*>(dst + off) = o;
  } else {
    int j = i - cv_total;
    if (j >= n4) return;
    int4 d = reinterpret_cast<const int4*>(dist)[j];
    int4 e = reinterpret_cast<const int4*>(edge)[j];
    ushort4 o;
    o.x = (unsigned short)(d.x | (e.x << 8));
    o.y = (unsigned short)(d.y | (e.y << 8));
    o.z = (unsigned short)(d.z | (e.z << 8));
    o.w = (unsigned short)(d.w | (e.w << 8));
    reinterpret_cast<ushort4*>(g_DE16)[j] = o;
  }
}

// ---------------- proj GEMM (double-buffered cp.async + ldmatrix) -------------
// MODE 0: z=blockIdx.z in {0,1,2} -> Qh/Kh/VhT.  MODE 1: out proj (f32 out).
template <int MODE>
__global__ __launch_bounds__(256) void proj_mma(
    const float* __restrict__ bias0, const float* __restrict__ bias1,
    const float* __restrict__ bias2, float* __restrict__ Cout) {
  extern __shared__ __half psm[];
  __half* Abuf[2] = { psm, psm + 128 * 72 };
  __half* Wbuf[2] = { psm + 2 * 128 * 72, psm + 2 * 128 * 72 + 64 * 72 };
  const int z = (MODE == 0) ? blockIdx.z : 3;
  const __half* A = (MODE == 0) ? g_In16[z] : g_OutH;
  const __half* W = g_W16[z];
  const float* bias = (MODE == 0) ? (z == 0 ? bias0 : (z == 1 ? bias1 : bias2)) : bias0;
  const int m0 = blockIdx.y * 128, n0 = blockIdx.x * 64;
  const int tid = threadIdx.x, lane = tid & 31, wid = tid >> 5;
  const int wm = wid & 3, wn = wid >> 2, g = lane >> 2, t4 = lane & 3;
  const int bbM = m0 >> 9, ii0 = m0 & 511;
  float c[2][4][4] = {};

  const int lrow = lane & 15, lcolB = (lane >> 4) * 16;
  const unsigned baseU = (unsigned)__cvta_generic_to_shared(psm);
  const unsigned aB[2] = { baseU + (wm * 32 + lrow) * 144 + lcolB,
                           baseU + 128 * 144 + (wm * 32 + lrow) * 144 + lcolB };
  const unsigned wB[2] = { baseU + 2 * 128 * 144 + (wn * 32 + lrow) * 144 + lcolB,
                           baseU + 2 * 128 * 144 + 64 * 144 + (wn * 32 + lrow) * 144 + lcolB };

  auto issue = [&](int s, int buf) {
#pragma unroll
    for (int i = 0; i < 4; i++) {
      int idx = tid + i * 256;
      int r = idx >> 3, c8 = (idx & 7) * 8;
      const __half* gp;
      if (MODE == 0) gp = A + (m0 + r) * 512 + s * 64 + c8;
      else {
        int n = m0 + r, bb = n >> 9, ii = n & 511;
        gp = g_OutH + ((bb * NH + s) * S + ii) * DK + c8;
      }
      cpa16(Abuf[buf] + r * 72 + c8, gp);
    }
#pragma unroll
    for (int i = 0; i < 2; i++) {
      int idx = tid + i * 256;
      int r = idx >> 3, c8 = (idx & 7) * 8;
      cpa16(Wbuf[buf] + r * 72 + c8, W + (n0 + r) * 512 + s * 64 + c8);
    }
    cp_commit();
  };

  issue(0, 0);
  for (int s = 0; s < 8; s++) {
    const int buf = s & 1;
    if (s < 7) { issue(s + 1, buf ^ 1); cp_wait1(); } else { cp_wait0(); }
    __syncthreads();
#pragma unroll
    for (int k16 = 0; k16 < 4; k16++) {
      unsigned a0[4], a1[4], q0[4], q1[4];
      ldsm_x4(a0, aB[buf] + k16 * 32);
      ldsm_x4(a1, aB[buf] + 16 * 144 + k16 * 32);
      ldsm_x4(q0, wB[buf] + k16 * 32);
      ldsm_x4(q1, wB[buf] + 16 * 144 + k16 * 32);
      { unsigned bb[2] = {q0[0], q0[2]}; mma_f16(c[0][0], a0, bb); mma_f16(c[1][0], a1, bb); }
      { unsigned bb[2] = {q0[1], q0[3]}; mma_f16(c[0][1], a0, bb); mma_f16(c[1][1], a1, bb); }
      { unsigned bb[2] = {q1[0], q1[2]}; mma_f16(c[0][2], a0, bb); mma_f16(c[1][2], a1, bb); }
      { unsigned bb[2] = {q1[1], q1[3]}; mma_f16(c[0][3], a0, bb); mma_f16(c[1][3], a1, bb); }
    }
    __syncthreads();
  }

  if (MODE == 0 && z == 2) {
    __half* Vst = psm;  // [64][136]
#pragma unroll
    for (int mi = 0; mi < 2; mi++)
#pragma unroll
      for (int ni = 0; ni < 4; ni++)
#pragma unroll
        for (int hf = 0; hf < 2; hf++) {
          const int rl = wm * 32 + mi * 16 + g + hf * 8;
          const int d = wn * 32 + ni * 8 + t4 * 2;
          Vst[d * 136 + rl]       = __float2half_rn(c[mi][ni][hf * 2 + 0] + bias[n0 + d]);
          Vst[(d + 1) * 136 + rl] = __float2half_rn(c[mi][ni][hf * 2 + 1] + bias[n0 + d + 1]);
        }
    __syncthreads();
    const int d = tid >> 2, q32 = tid & 3;
    const uint4* srcp = reinterpret_cast<const uint4*>(Vst + d * 136 + q32 * 32);
    __half* dstp = g_VhT + (size_t)((bbM * NH + (n0 >> 6)) * DK + d) * S + ii0 + q32 * 32;
#pragma unroll
    for (int i = 0; i < 4; i++) reinterpret_cast<uint4*>(dstp)[i] = srcp[i];
    return;
  }

#pragma unroll
  for (int mi = 0; mi < 2; mi++)
#pragma unroll
    for (int ni = 0; ni < 4; ni++)
#pragma unroll
      for (int hf = 0; hf < 2; hf++) {
        const int row = m0 + wm * 32 + mi * 16 + g + hf * 8;
        const int col = n0 + wn * 32 + ni * 8 + t4 * 2;
        const float v0 = c[mi][ni][hf * 2 + 0] + bias[col];
        const float v1 = c[mi][ni][hf * 2 + 1] + bias[col + 1];
        if (MODE == 1) {
          *reinterpret_cast<float2*>(&Cout[row * 512 + col]) = make_float2(v0, v1);
        } else {
          const int bb = row >> 9, ii = row & 511, h = col >> 6, d = col & 63;
          __half* dst = (z == 0) ? g_Qh : g_Kh;
          *reinterpret_cast<__half2*>(&dst[(((bb * NH + h) * S) + ii) * DK + d]) =
              __floats2half2_rn(v0, v1);
        }
      }
}

// ---------------- tables: QHop/KHop/EB via fp16 mma ---------------------------
__global__ __launch_bounds__(256) void tables_mma(
    const float* __restrict__ qhe, const float* __restrict__ qee,
    const float* __restrict__ khe, const float* __restrict__ kee) {
  __shared__ unsigned Qs[64][36];
  __shared__ unsigned Ks2[64][36];
  __shared__ unsigned Eq[48][36];
  __shared__ unsigned Ek[48][36];
  const int bh = blockIdx.x, h = bh & 7;
  const int i0 = blockIdx.y * 64;
  const int tid = threadIdx.x;
  const int lane = tid & 31, wid = tid >> 5;
  const int wm = wid & 3, wn = wid >> 2;
  const int g = lane >> 2, t4 = lane & 3;

  for (int i = tid; i < 64 * 16; i += 256) {
    const int r = i >> 4, u = i & 15;
    uint2 q = *reinterpret_cast<const uint2*>(&g_Qh[(bh * S + i0 + r) * DK + u * 4]);
    uint2 k = *reinterpret_cast<const uint2*>(&g_Kh[(bh * S + i0 + r) * DK + u * 4]);
    Qs[r][u * 2] = q.x;  Qs[r][u * 2 + 1] = q.y;
    Ks2[r][u * 2] = k.x; Ks2[r][u * 2 + 1] = k.y;
  }
  for (int i = tid; i < 48 * 16; i += 256) {
    const int r = i >> 4, cc = (i & 15) * 4;
    const float* sq = (r < TH) ? &qhe[r * HID + h * DK + cc] : &qee[(r - TH) * HID + h * DK + cc];
    const float* sk = (r < TH) ? &khe[r * HID + h * DK + cc] : &kee[(r - TH) * HID + h * DK + cc];
    float4 vq = *reinterpret_cast<const float4*>(sq);
    float4 vk = *reinterpret_cast<const float4*>(sk);
    Eq[r][(cc >> 1)]     = pack_half2(vq.x, vq.y);
    Eq[r][(cc >> 1) + 1] = pack_half2(vq.z, vq.w);
    Ek[r][(cc >> 1)]     = pack_half2(vk.x, vk.y);
    Ek[r][(cc >> 1) + 1] = pack_half2(vk.z, vk.w);
  }
  __syncthreads();

  float cQ[3][4] = {}, cK[3][4] = {};
#pragma unroll
  for (int ks = 0; ks < 4; ks++) {
    const int kw = ks * 8;
    const int rr = wm * 16 + g;
    unsigned aQ[4], aK[4], bQ[3][2], bK[3][2];
    aQ[0] = Qs[rr][kw + t4];      aQ[1] = Qs[rr + 8][kw + t4];
    aQ[2] = Qs[rr][kw + 4 + t4];  aQ[3] = Qs[rr + 8][kw + 4 + t4];
    aK[0] = Ks2[rr][kw + t4];     aK[1] = Ks2[rr + 8][kw + t4];
    aK[2] = Ks2[rr][kw + 4 + t4]; aK[3] = Ks2[rr + 8][kw + 4 + t4];
#pragma unroll
    for (int ni = 0; ni < 3; ni++) {
      const int cc = wn * 24 + ni * 8 + g;
      bQ[ni][0] = Eq[cc][kw + t4]; bQ[ni][1] = Eq[cc][kw + 4 + t4];
      bK[ni][0] = Ek[cc][kw + t4]; bK[ni][1] = Ek[cc][kw + 4 + t4];
    }
#pragma unroll
    for (int ni = 0; ni < 3; ni++) {
      mma_f16(cQ[ni], aQ, bQ[ni]);
      mma_f16(cK[ni], aK, bK[ni]);
    }
  }
#pragma unroll
  for (int ni = 0; ni < 3; ni++)
#pragma unroll
    for (int hf = 0; hf < 2; hf++) {
      const int row = i0 + wm * 16 + g + hf * 8;
      const int col = wn * 24 + ni * 8 + t4 * 2;
      const float q0 = cQ[ni][hf * 2], q1 = cQ[ni][hf * 2 + 1];
      const float k0 = cK[ni][hf * 2], k1 = cK[ni][hf * 2 + 1];
      if (col < TH) {
        *reinterpret_cast<__half2*>(&g_QHop16[(bh * S + row) * TH + col]) =
            __floats2half2_rn(q0, q1);
        *reinterpret_cast<float2*>(&g_KHop32[(bh * S + row) * TH + col]) =
            make_float2(k0, k1);
      } else {
        *reinterpret_cast<__half2*>(&g_EB16[(bh * S + row) * TE + (col - TH)]) =
            __floats2half2_rn(q0 + k0, q1 + k1);
      }
    }
}

// ---------------- fused flash attention + bins ---------------------------------
struct FSmem {
  unsigned Qs[64][36];       // stride 144B (LDSM conflict-free)
  unsigned Ks[128][36];
  unsigned Vt[64][68];       // stride 272B; V^T chunk [d][j]; tables in epilogue
  unsigned Ph[64][68];       // half P; normalized bins in epilogue
  float KHs[128][36];        // f32, cp.async target, odd-ish bank stride
  float rowhop[64][33];
  float rowedge[64][17];
  float binsH[64][33];
  float binsE[64][17];
  float rowl[64];
};

__global__ __launch_bounds__(512) void fused_attn(
    const float* __restrict__ vhe, const float* __restrict__ vee) {
  extern __shared__ char smem_raw[];
  FSmem& sm = *reinterpret_cast<FSmem*>(smem_raw);
  const int bh = blockIdx.x, b = bh >> 3, h = bh & 7;
  const int i0 = blockIdx.y * 64;
  const int tid = threadIdx.x;
  const int lane = tid & 31, wid = tid >> 5;
  const int g = lane >> 2, t4 = lane & 3;
  const int wmq = wid & 3, wnq = wid >> 2;  // QK: 16 x 32
  const int wma = wid & 3, wna = wid >> 2;  // AV: 16 x 16

  const int lrow = lane & 15, lcolB = (lane >> 4) * 16;
  const unsigned qs_b = (unsigned)__cvta_generic_to_shared(&sm.Qs[0][0]) +
                        (wmq * 16 + lrow) * 144 + lcolB;
  const unsigned ks_b0 = (unsigned)__cvta_generic_to_shared(&sm.Ks[0][0]) +
                         (wnq * 32 + lrow) * 144 + lcolB;
  const unsigned ks_b1 = ks_b0 + 16 * 144;
  const unsigned ph_b = (unsigned)__cvta_generic_to_shared(&sm.Ph[0][0]) +
                        (wma * 16 + lrow) * 272 + lcolB;
  const unsigned vt_b = (unsigned)__cvta_generic_to_shared(&sm.Vt[0][0]) +
                        (wna * 16 + lrow) * 272 + lcolB;

  for (int i = tid; i < 64 * 16; i += 512) {
    const int r = i >> 4, u = i & 15;
    uint2 q = *reinterpret_cast<const uint2*>(&g_Qh[(bh * S + i0 + r) * DK + u * 4]);
    sm.Qs[r][u * 2] = q.x; sm.Qs[r][u * 2 + 1] = q.y;
  }
  for (int i = tid; i < 64 * 8; i += 512) {  // rowhop f32 from half
    const int r = i >> 3, u = i & 7;
    uint2 v = *reinterpret_cast<const uint2*>(&g_QHop16[(bh * S + i0 + r) * TH + u * 4]);
    __half2 h0 = *reinterpret_cast<__half2*>(&v.x);
    __half2 h1 = *reinterpret_cast<__half2*>(&v.y);
    sm.rowhop[r][u * 4 + 0] = __low2float(h0);
    sm.rowhop[r][u * 4 + 1] = __high2float(h0);
    sm.rowhop[r][u * 4 + 2] = __low2float(h1);
    sm.rowhop[r][u * 4 + 3] = __high2float(h1);
  }
  for (int i = tid; i < 64 * 4; i += 512) {  // rowedge f32 from half
    const int r = i >> 2, u = i & 3;
    uint2 v = *reinterpret_cast<const uint2*>(&g_EB16[(bh * S + i0 + r) * TE + u * 4]);
    __half2 h0 = *reinterpret_cast<__half2*>(&v.x);
    __half2 h1 = *reinterpret_cast<__half2*>(&v.y);
    sm.rowedge[r][u * 4 + 0] = __low2float(h0);
    sm.rowedge[r][u * 4 + 1] = __high2float(h0);
    sm.rowedge[r][u * 4 + 2] = __low2float(h1);
    sm.rowedge[r][u * 4 + 3] = __high2float(h1);
  }
  for (int i = tid; i < 64 * 33; i += 512) sm.binsH[i / 33][i % 33] = 0.f;
  for (int i = tid; i < 64 * 17; i += 512) sm.binsE[i / 17][i % 17] = 0.f;
  if (tid < 64) sm.rowl[tid] = 0.f;

  float co[2][4] = {};
  const int rrq = wmq * 16 + g;
  const int rra = wma * 16 + g;

  for (int ch = 0; ch < 4; ch++) {
    const int j0 = ch * 128;
    // ---- cp.async chunk loads: K, V^T, KHop ----
#pragma unroll
    for (int i = 0; i < 2; i++) {
      const int idx = tid + i * 512;
      { const int r = idx >> 3, c = idx & 7;
        cpa16((char*)&sm.Ks[r][0] + c * 16, &g_Kh[(bh * S + j0 + r) * DK + c * 8]); }
      { const int d = idx >> 4, c = idx & 15;
        cpa16((char*)&sm.Vt[d][0] + c * 16, &g_VhT[(size_t)(bh * DK + d) * S + j0 + c * 8]); }
      { const int r = idx >> 3, c = idx & 7;
        cpa16((char*)&sm.KHs[r][0] + c * 16, &g_KHop32[(bh * S + j0 + r) * TH + c * 4]); }
    }
    cp_commit(); cp_wait0();
    __syncthreads();

    // ---- QK mma (ldmatrix fragments) ----
    float cq[4][4] = {};
#pragma unroll
    for (int ks = 0; ks < 4; ks++) {
      unsigned a[4], p0[4], p1[4];
      ldsm_x4(a, qs_b + ks * 32);
      ldsm_x4(p0, ks_b0 + ks * 32);
      ldsm_x4(p1, ks_b1 + ks * 32);
      { unsigned bb[2] = {p0[0], p0[2]}; mma_f16(cq[0], a, bb); }
      { unsigned bb[2] = {p0[1], p0[3]}; mma_f16(cq[1], a, bb); }
      { unsigned bb[2] = {p1[0], p1[2]}; mma_f16(cq[2], a, bb); }
      { unsigned bb[2] = {p1[1], p1[3]}; mma_f16(cq[3], a, bb); }
    }

    // ---- fused epilogue: de from L1, bias gather + exp2 + bins + sums ----
    {
      const int r0 = rrq, r1 = rrq + 8;
      const size_t deb0 = ((size_t)b * S + i0 + r0) * S + j0;
      const size_t deb1 = ((size_t)b * S + i0 + r1) * S + j0;
      float s0 = 0.f, s1 = 0.f;
#pragma unroll
      for (int ni = 0; ni < 4; ni++) {
        const int jl = wnq * 32 + ni * 8 + t4 * 2;
        const unsigned de0 = *reinterpret_cast<const unsigned*>(&g_DE16[deb0 + jl]);
        const unsigned de1 = *reinterpret_cast<const unsigned*>(&g_DE16[deb1 + jl]);
        {
          const int dhA = de0 & 0xFF, eeA = (de0 >> 8) & 0xFF;
          const int dhB = (de0 >> 16) & 0xFF, eeB = de0 >> 24;
          const float scA = (cq[ni][0] + sm.rowhop[r0][dhA] + sm.KHs[jl][dhA] +
                             sm.rowedge[r0][eeA]) * SC2;
          const float scB = (cq[ni][1] + sm.rowhop[r0][dhB] + sm.KHs[jl + 1][dhB] +
                             sm.rowedge[r0][eeB]) * SC2;
          const float pA = fast_exp2(scA), pB = fast_exp2(scB);
          sm.Ph[r0][jl >> 1] = pack_half2(pA, pB);
          atomicAdd(&sm.binsH[r0][dhA], pA); atomicAdd(&sm.binsE[r0][eeA], pA);
          atomicAdd(&sm.binsH[r0][dhB], pB); atomicAdd(&sm.binsE[r0][eeB], pB);
          s0 += pA + pB;
        }
        {
          const int dhA = de1 & 0xFF, eeA = (de1 >> 8) & 0xFF;
          const int dhB = (de1 >> 16) & 0xFF, eeB = de1 >> 24;
          const float scA = (cq[ni][2] + sm.rowhop[r1][dhA] + sm.KHs[jl][dhA] +
                             sm.rowedge[r1][eeA]) * SC2;
          const float scB = (cq[ni][3] + sm.rowhop[r1][dhB] + sm.KHs[jl + 1][dhB] +
                             sm.rowedge[r1][eeB]) * SC2;
          const float pA = fast_exp2(scA), pB = fast_exp2(scB);
          sm.Ph[r1][jl >> 1] = pack_half2(pA, pB);
          atomicAdd(&sm.binsH[r1][dhA], pA); atomicAdd(&sm.binsE[r1][eeA], pA);
          atomicAdd(&sm.binsH[r1][dhB], pB); atomicAdd(&sm.binsE[r1][eeB], pB);
          s1 += pA + pB;
        }
      }
      s0 += __shfl_xor_sync(0xffffffffu, s0, 1);
      s0 += __shfl_xor_sync(0xffffffffu, s0, 2);
      s1 += __shfl_xor_sync(0xffffffffu, s1, 1);
      s1 += __shfl_xor_sync(0xffffffffu, s1, 2);
      if (t4 == 0) {
        atomicAdd(&sm.rowl[r0], s0);
        atomicAdd(&sm.rowl[r1], s1);
      }
    }
    __syncthreads();

    // ---- P@V mma (ldmatrix fragments) ----
#pragma unroll
    for (int ks = 0; ks < 8; ks++) {
      unsigned a[4], bb4[4];
      ldsm_x4(a, ph_b + ks * 32);
      ldsm_x4(bb4, vt_b + ks * 32);
      { unsigned bb[2] = {bb4[0], bb4[2]}; mma_f16(co[0], a, bb); }
      { unsigned bb[2] = {bb4[1], bb4[3]}; mma_f16(co[1], a, bb); }
    }
    __syncthreads();
  }

  // ---- epilogue: normalize O, add normalized-bins GEMMs, store ----
  const float inv0 = 1.f / sm.rowl[rra];
  const float inv1 = 1.f / sm.rowl[rra + 8];
#pragma unroll
  for (int ni = 0; ni < 2; ni++) {
    co[ni][0] *= inv0; co[ni][1] *= inv0;
    co[ni][2] *= inv1; co[ni][3] *= inv1;
  }
  for (int i = tid; i < 64 * 48; i += 512) {
    const int r = i / 48, t = i % 48;
    const float invr = 1.f / sm.rowl[r];
    const float v = ((t < TH) ? sm.binsH[r][t] : sm.binsE[r][t - TH]) * invr;
    reinterpret_cast<__half*>(&sm.Ph[r][0])[t] = __float2half_rn(v);
  }
  for (int i = tid; i < 64 * 24; i += 512) {
    const int d = i / 24, tw = i % 24;
    const int t0 = tw * 2, t1 = t0 + 1;
    const float x = (t0 < TH) ? vhe[t0 * HID + h * DK + d] : vee[(t0 - TH) * HID + h * DK + d];
    const float y = (t1 < TH) ? vhe[t1 * HID + h * DK + d] : vee[(t1 - TH) * HID + h * DK + d];
    sm.Vt[d][tw] = pack_half2(x, y);
  }
  __syncthreads();
#pragma unroll
  for (int ks = 0; ks < 3; ks++) {
    unsigned a[4], bb4[4];
    ldsm_x4(a, ph_b + ks * 32);
    ldsm_x4(bb4, vt_b + ks * 32);
    { unsigned bb[2] = {bb4[0], bb4[2]}; mma_f16(co[0], a, bb); }
    { unsigned bb[2] = {bb4[1], bb4[3]}; mma_f16(co[1], a, bb); }
  }

#pragma unroll
  for (int ni = 0; ni < 2; ni++) {
    const int col = wna * 16 + ni * 8 + t4 * 2;
    const int row0 = i0 + wma * 16 + g;
    *reinterpret_cast<__half2*>(&g_OutH[(bh * S + row0) * DK + col]) =
        __floats2half2_rn(co[ni][0], co[ni][1]);
    *reinterpret_cast<__half2*>(&g_OutH[(bh * S + row0 + 8) * DK + col]) =
        __floats2half2_rn(co[ni][2], co[ni][3]);
  }
}

// ---------------- launcher ----------------------------------------------------
extern "C" void kernel_launch(void* const* d_in, const int* in_sizes, int n_in,
                              void* d_out, int out_size) {
  (void)in_sizes; (void)n_in; (void)out_size;
  const float* q   = (const float*)d_in[0];
  const float* k   = (const float*)d_in[1];
  const float* v   = (const float*)d_in[2];
  const float* qhe = (const float*)d_in[3];
  const float* qee = (const float*)d_in[4];
  const float* khe = (const float*)d_in[5];
  const float* kee = (const float*)d_in[6];
  const float* vhe = (const float*)d_in[7];
  const float* vee = (const float*)d_in[8];
  const int* dist  = (const int*)d_in[9];
  const int* edge  = (const int*)d_in[10];
  const float* Wq = (const float*)d_in[11], *bq = (const float*)d_in[12];
  const float* Wk = (const float*)d_in[13], *bk = (const float*)d_in[14];
  const float* Wv = (const float*)d_in[15], *bv = (const float*)d_in[16];
  const float* Wo = (const float*)d_in[17], *bo = (const float*)d_in[18];
  float* out = (float*)d_out;

  const int proj_smem = (2 * 128 * 72 + 2 * 64 * 72) * 2;  // 55296
  const int fused_smem = (int)sizeof(FSmem);                // ~107 KB -> 2 CTA/SM
  cudaFuncSetAttribute(proj_mma<0>, cudaFuncAttributeMaxDynamicSharedMemorySize, proj_smem);
  cudaFuncSetAttribute(proj_mma<1>, cudaFuncAttributeMaxDynamicSharedMemorySize, proj_smem);
  cudaFuncSetAttribute(fused_attn, cudaFuncAttributeMaxDynamicSharedMemorySize, fused_smem);

  const int QU = QN / 8, WU = WN / 8;
  const int prep_total = 3 * QU + 4 * WU + B * S * S / 4;
  prep_kernel<<<(prep_total + 255) / 256, 256>>>(q, k, v, Wq, Wk, Wv, Wo, dist, edge);

  proj_mma<0><<<dim3(8, 64, 3), 256, proj_smem>>>(bq, bk, bv, nullptr);
  tables_mma<<<dim3(BH, 8), 256>>>(qhe, qee, khe, kee);
  fused_attn<<<dim3(BH, 8), 512, fused_smem>>>(vhe, vee);
  proj_mma<1><<<dim3(8, 64, 1), 256, proj_smem>>>(bo, nullptr, nullptr, out);
}